// round 9
// baseline (speedup 1.0000x reference)
#include <cuda_runtime.h>
#include <stdint.h>

#define NT 256
#define TILE 128        // points per block
#define KC 4            // k-chunk
#define NCHUNK 8        // 32 / KC

// Folded weights, duplicated: Pg[kj][o] = {v,v}. 48 KB.
__device__ float2 Pg[192 * 32];

__device__ __forceinline__ long long fma2(long long a, long long b, long long c) {
    long long d;
    asm("fma.rn.f32x2 %0, %1, %2, %3;" : "=l"(d) : "l"(a), "l"(b), "l"(c));
    return d;
}
__device__ __forceinline__ long long mul2(long long a, long long b) {
    long long d;
    asm("mul.rn.f32x2 %0, %1, %2;" : "=l"(d) : "l"(a), "l"(b));
    return d;
}

__global__ void hermite_prep(const float* __restrict__ sig,
                             const float* __restrict__ W) {
    int i = blockIdx.x * blockDim.x + threadIdx.x;
    if (i >= 192 * 32) return;
    int o  = i & 31;
    int kj = i >> 5;
    int k  = kj / 6;
    int j  = kj - k * 6;
    float val = 0.0f;
    if (o < 31) {
        float s   = sig[k];
        float s2  = s * s;
        float is2 = 1.0f / (s2 + 1e-6f);
        float is4 = 1.0f / (s2 * s2 + 1e-6f);
        const float* Wk = W + k * 186 + o;           // [k][h][o], H=6, O=31
        if      (j == 0) val = Wk[0] - is2 * (Wk[93] + Wk[155]);
        else if (j == 1) val = -is2 * Wk[62];        // * g*dx
        else if (j == 2) val = -is2 * Wk[31];        // * g*dy
        else if (j == 3) val = is4 * Wk[155];        // * g*dx^2
        else if (j == 4) val = is4 * Wk[124];        // * g*dx*dy
        else             val = is4 * Wk[93];         // * g*dy^2
    }
    Pg[kj * 32 + o] = make_float2(val, val);
}

extern __shared__ __align__(16) float smem[];
// dxs/dys/gs : [KC][128] each  (3 x 2048 B)
// Psh        : [192][64] dup   (49152 B)
// epilogue stage[128][33] (16896 B) reuses the front of smem
#define RAW_FLOATS (KC * TILE)
#define SMEM_BYTES ((3 * RAW_FLOATS + 192 * 64) * 4)   // 55296

// keeps 8B granularity; pt bits 0-2 and kl bits 3-4 stay disjoint in the bank id
__device__ __forceinline__ int swz2(int p, int kl) {
    return p ^ ((p & 32) >> 3) ^ (kl << 3);
}

__global__ void __launch_bounds__(NT, 4)
hermite_main(const float* __restrict__ mlp,
             const float* __restrict__ cd,
             const float* __restrict__ gw,
             float* __restrict__ out,
             int total /* B*N */) {
    float* dxs = smem;
    float* dys = smem + RAW_FLOATS;
    float* gs  = smem + 2 * RAW_FLOATS;
    float* Psh = smem + 3 * RAW_FLOATS;

    const int tid   = threadIdx.x;
    const int wid   = tid >> 5;
    const int lane  = tid & 31;
    const int og    = wid & 3;           // outputs og*8 .. og*8+7
    const int ph    = wid >> 2;          // point half
    const int p0    = ph * 64 + lane * 2;
    const int tile0 = blockIdx.x * TILE;

    // ---- Load duplicated P into SMEM (coalesced, 12 float4/thread) ----
    {
        const float4* src = reinterpret_cast<const float4*>(Pg);
        float4*       dst = reinterpret_cast<float4*>(Psh);
        for (int i = tid; i < (192 * 64) / 4; i += NT) dst[i] = src[i];
    }

    long long acc[8];
#pragma unroll
    for (int oo = 0; oo < 8; oo++) acc[oo] = 0ll;

    // warp-uniform P base: 16 ull2 per kj row; this warp reads og*4 .. og*4+3
    const ulonglong2* Pw = reinterpret_cast<const ulonglong2*>(Psh) + og * 4;

#pragma unroll 1
    for (int c = 0; c < NCHUNK; c++) {
        __syncthreads();   // P ready (c=0) / previous chunk's reads done

        // ---- Phase 1: stage raw dx,dy,g (kl fastest -> cd 32B sectors) ----
#pragma unroll
        for (int it = 0; it < 2; it++) {
            int item = tid + it * NT;
            int kl   = item & (KC - 1);
            int pt   = item >> 2;
            int n    = tile0 + pt;
            int k    = c * KC + kl;
            float dx = 0.0f, dy = 0.0f, g = 0.0f;
            if (n < total) {
                float2 cc = reinterpret_cast<const float2*>(cd)[(size_t)n * 32 + k];
                dx = cc.x; dy = cc.y;
                g  = gw[(size_t)n * 32 + k];
            }
            int col = swz2(pt, kl);
            dxs[kl * TILE + col] = dx;
            dys[kl * TILE + col] = dy;
            gs [kl * TILE + col] = g;
        }
        __syncthreads();

        // ---- Phase 2: 2 pts (one f32x2 pair) x 8 outs; prefetched M ----
        long long cg, cdx, cdy;
        {
            int col = swz2(p0, 0);
            cg  = *reinterpret_cast<const long long*>(gs  + col);
            cdx = *reinterpret_cast<const long long*>(dxs + col);
            cdy = *reinterpret_cast<const long long*>(dys + col);
        }
#pragma unroll
        for (int kl = 0; kl < KC; kl++) {
            long long ng = cg, ndx = cdx, ndy = cdy;
            if (kl + 1 < KC) {
                int col = (kl + 1) * TILE + swz2(p0, kl + 1);
                ng  = *reinterpret_cast<const long long*>(gs  + col);
                ndx = *reinterpret_cast<const long long*>(dxs + col);
                ndy = *reinterpret_cast<const long long*>(dys + col);
            }
            const ulonglong2* Pk = Pw + ((c * KC + kl) * 6) * 16;

#define DO_J(jj, MV) do {                                                      \
    ulonglong2 q0 = Pk[(jj) * 16];                                             \
    ulonglong2 q1 = Pk[(jj) * 16 + 1];                                         \
    ulonglong2 q2 = Pk[(jj) * 16 + 2];                                         \
    ulonglong2 q3 = Pk[(jj) * 16 + 3];                                         \
    acc[0] = fma2(MV, (long long)q0.x, acc[0]);                                \
    acc[1] = fma2(MV, (long long)q0.y, acc[1]);                                \
    acc[2] = fma2(MV, (long long)q1.x, acc[2]);                                \
    acc[3] = fma2(MV, (long long)q1.y, acc[3]);                                \
    acc[4] = fma2(MV, (long long)q2.x, acc[4]);                                \
    acc[5] = fma2(MV, (long long)q2.y, acc[5]);                                \
    acc[6] = fma2(MV, (long long)q3.x, acc[6]);                                \
    acc[7] = fma2(MV, (long long)q3.y, acc[7]);                                \
} while (0)

            long long m1 = mul2(cg, cdx);
            long long m2 = mul2(cg, cdy);
            DO_J(0, cg);                       // coeff 1
            DO_J(1, m1);                       // g*dx
            DO_J(2, m2);                       // g*dy
            long long mt = mul2(m1, cdx);
            DO_J(3, mt);                       // g*dx^2
            mt = mul2(m1, cdy);
            DO_J(4, mt);                       // g*dx*dy
            mt = mul2(m2, cdy);
            DO_J(5, mt);                       // g*dy^2
#undef DO_J
            cg = ng; cdx = ndx; cdy = ndy;
        }
    }

    // ---- Epilogue: stage mix (reuse smem), then coalesced I/O ----
    __syncthreads();
    float* stage = smem;              // [128][33] = 16896 B
#pragma unroll
    for (int oo = 0; oo < 8; oo++) {
        long long a = acc[oo];
        float lo = __uint_as_float((unsigned)((unsigned long long)a & 0xffffffffu));
        float hi = __uint_as_float((unsigned)((unsigned long long)a >> 32));
        int o = og * 8 + oo;
        stage[p0 * 33 + o]       = lo;
        stage[(p0 + 1) * 33 + o] = hi;
    }
    __syncthreads();

    size_t lim  = (size_t)total * 31;
    size_t base = (size_t)tile0 * 31;
    for (int e = tid; e < TILE * 31; e += NT) {
        size_t gidx = base + e;
        if (gidx < lim) {
            int rr = e / 31;
            int o  = e - rr * 31;
            out[gidx] = mlp[gidx] * stage[rr * 33 + o];
        }
    }
}

extern "C" void kernel_launch(void* const* d_in, const int* in_sizes, int n_in,
                              void* d_out, int out_size) {
    const float* mlp = (const float*)d_in[0];  // [B,N,31]
    const float* cd  = (const float*)d_in[1];  // [B,N,32,2]
    const float* sig = (const float*)d_in[2];  // [32]
    const float* gw  = (const float*)d_in[3];  // [B,N,32]
    const float* W   = (const float*)d_in[4];  // [32,6,31]

    int total  = in_sizes[3] / 32;             // B*N
    int blocks = (total + TILE - 1) / TILE;    // 2048

    hermite_prep<<<(192 * 32 + 255) / 256, 256>>>(sig, W);

    cudaFuncSetAttribute(hermite_main,
                         cudaFuncAttributeMaxDynamicSharedMemorySize, SMEM_BYTES);
    hermite_main<<<blocks, NT, SMEM_BYTES>>>(mlp, cd, gw, (float*)d_out, total);
}

// round 10
// speedup vs baseline: 1.4441x; 1.4441x over previous
#include <cuda_runtime.h>
#include <stdint.h>

#define NT 128
#define TILE 256        // points per block
#define KC 4            // k-chunk
#define NCHUNK 8        // 32 / KC
#define ITERS ((TILE * KC) / NT)   // 8 phase-1 items per thread per chunk

// Raw folded weights P[kj][o], kj = k*6+j, o padded to 32. 24 KB.
__device__ float Pg[192 * 32];

__device__ __forceinline__ long long fma2(long long a, long long b, long long c) {
    long long d;
    asm("fma.rn.f32x2 %0, %1, %2, %3;" : "=l"(d) : "l"(a), "l"(b), "l"(c));
    return d;
}
__device__ __forceinline__ long long mul2(long long a, long long b) {
    long long d;
    asm("mul.rn.f32x2 %0, %1, %2;" : "=l"(d) : "l"(a), "l"(b));
    return d;
}
__device__ __forceinline__ long long pack2(float x) {
    long long d;
    asm("mov.b64 %0, {%1, %1};" : "=l"(d) : "f"(x));
    return d;
}
#define LL(f4, half) (*reinterpret_cast<const long long*>(&(f4).half))

__global__ void hermite_prep(const float* __restrict__ sig,
                             const float* __restrict__ W) {
    int i = blockIdx.x * blockDim.x + threadIdx.x;
    if (i >= 192 * 32) return;
    int o  = i & 31;
    int kj = i >> 5;
    int k  = kj / 6;
    int j  = kj - k * 6;
    float val = 0.0f;
    if (o < 31) {
        float s   = sig[k];
        float s2  = s * s;
        float is2 = 1.0f / (s2 + 1e-6f);
        float is4 = 1.0f / (s2 * s2 + 1e-6f);
        const float* Wk = W + k * 186 + o;           // [k][h][o], H=6, O=31
        if      (j == 0) val = Wk[0] - is2 * (Wk[93] + Wk[155]);
        else if (j == 1) val = -is2 * Wk[62];        // * g*dx
        else if (j == 2) val = -is2 * Wk[31];        // * g*dy
        else if (j == 3) val = is4 * Wk[155];        // * g*dx^2
        else if (j == 4) val = is4 * Wk[124];        // * g*dx*dy
        else             val = is4 * Wk[93];         // * g*dy^2
    }
    Pg[kj * 32 + o] = val;
}

extern __shared__ __align__(16) float smem[];
// dxs/dys/gs : [KC][256] each (3 x 4096 B = 12288 B), swizzled cols
// Psh        : [192][32] raw  (24576 B)
// epilogue stage[256][33] = 33792 B <= 36864 B total (P dead by then)
#define RAW_FLOATS (KC * TILE)
#define SMEM_BYTES (3 * RAW_FLOATS * 4 + 192 * 32 * 4)

// STS: lane kl bits 3-4, pt bits 0-2 -> 32 distinct banks. 16B-preserving.
__device__ __forceinline__ int swz(int p, int kl) {
    return p ^ ((p & 32) >> 3) ^ (kl << 3);
}

__global__ void __launch_bounds__(NT, 4)
hermite_main(const float* __restrict__ mlp,
             const float* __restrict__ cd,
             const float* __restrict__ gw,
             float* __restrict__ out,
             int total /* B*N */) {
    float* dxs = smem;
    float* dys = smem + RAW_FLOATS;
    float* gs  = smem + 2 * RAW_FLOATS;
    float* Psh = smem + 3 * RAW_FLOATS;

    const int tid   = threadIdx.x;
    const int wid   = tid >> 5;        // o-group: outputs wid*8 .. wid*8+7
    const int lane  = tid & 31;
    const int pg8   = lane * 8;        // this thread's 8 points
    const int tile0 = blockIdx.x * TILE;

    // ---- Prefetch chunk 0 (overlaps the P copy below) ----
    float pdx[ITERS], pdy[ITERS], pg[ITERS];
#define PREFETCH(c) do {                                                       \
    _Pragma("unroll")                                                          \
    for (int it = 0; it < ITERS; it++) {                                       \
        int item = tid + it * NT;                                              \
        int kl   = item & (KC - 1);                                            \
        int pt   = item >> 2;                                                  \
        int n    = tile0 + pt;                                                 \
        int k    = (c) * KC + kl;                                              \
        float dx = 0.0f, dy = 0.0f, g = 0.0f;                                  \
        if (n < total) {                                                       \
            float2 cc = reinterpret_cast<const float2*>(cd)[(size_t)n * 32 + k]; \
            dx = cc.x; dy = cc.y;                                              \
            g  = gw[(size_t)n * 32 + k];                                       \
        }                                                                      \
        pdx[it] = dx; pdy[it] = dy; pg[it] = g;                                \
    }                                                                          \
} while (0)

    PREFETCH(0);

    // ---- Load raw P into SMEM (coalesced) ----
    {
        const float4* src = reinterpret_cast<const float4*>(Pg);
        float4*       dst = reinterpret_cast<float4*>(Psh);
        for (int i = tid; i < (192 * 32) / 4; i += NT) dst[i] = src[i];
    }

    long long acc[4][8];
#pragma unroll
    for (int pp = 0; pp < 4; pp++)
#pragma unroll
        for (int oo = 0; oo < 8; oo++) acc[pp][oo] = 0ll;

#pragma unroll 1
    for (int c = 0; c < NCHUNK; c++) {
        __syncthreads();   // P ready (c=0) / previous chunk's reads done

        // ---- STS chunk c from registers (short burst, no LDG stall) ----
#pragma unroll
        for (int it = 0; it < ITERS; it++) {
            int item = tid + it * NT;
            int kl   = item & (KC - 1);
            int pt   = item >> 2;
            int col  = swz(pt, kl);
            dxs[kl * TILE + col] = pdx[it];
            dys[kl * TILE + col] = pdy[it];
            gs [kl * TILE + col] = pg[it];
        }
        __syncthreads();

        // ---- Issue next chunk's LDGs; latency hidden under phase 2 ----
        if (c + 1 < NCHUNK) PREFETCH(c + 1);

        // ---- Phase 2: 8 pts x 8 outs; P loads warp-uniform (dedup) ----
#pragma unroll 1
        for (int kl = 0; kl < KC; kl++) {
            int colA = swz(pg8, kl);
            int colB = swz(pg8 + 4, kl);
            float4 ga  = *reinterpret_cast<const float4*>(gs  + kl * TILE + colA);
            float4 gb  = *reinterpret_cast<const float4*>(gs  + kl * TILE + colB);
            float4 dxa = *reinterpret_cast<const float4*>(dxs + kl * TILE + colA);
            float4 dxb = *reinterpret_cast<const float4*>(dxs + kl * TILE + colB);
            float4 dya = *reinterpret_cast<const float4*>(dys + kl * TILE + colA);
            float4 dyb = *reinterpret_cast<const float4*>(dys + kl * TILE + colB);

            long long gpp[4] = { LL(ga, x), LL(ga, z), LL(gb, x), LL(gb, z) };
            long long dxp[4] = { LL(dxa, x), LL(dxa, z), LL(dxb, x), LL(dxb, z) };
            long long dyp[4] = { LL(dya, x), LL(dya, z), LL(dyb, x), LL(dyb, z) };

            const float* Pj = Psh + ((c * KC + kl) * 6) * 32 + wid * 8;

#define DO_J(jj, MV) do {                                                      \
    float4 pa = *reinterpret_cast<const float4*>(Pj + (jj) * 32);              \
    float4 pb = *reinterpret_cast<const float4*>(Pj + (jj) * 32 + 4);          \
    const float* pf = &pa.x;                                                   \
    _Pragma("unroll")                                                          \
    for (int oo = 0; oo < 4; oo++) {                                           \
        long long pd = pack2(pf[oo]);                                          \
        acc[0][oo] = fma2((MV)[0], pd, acc[0][oo]);                            \
        acc[1][oo] = fma2((MV)[1], pd, acc[1][oo]);                            \
        acc[2][oo] = fma2((MV)[2], pd, acc[2][oo]);                            \
        acc[3][oo] = fma2((MV)[3], pd, acc[3][oo]);                            \
    }                                                                          \
    const float* pq = &pb.x;                                                   \
    _Pragma("unroll")                                                          \
    for (int oo = 0; oo < 4; oo++) {                                           \
        long long pd = pack2(pq[oo]);                                          \
        acc[0][4 + oo] = fma2((MV)[0], pd, acc[0][4 + oo]);                    \
        acc[1][4 + oo] = fma2((MV)[1], pd, acc[1][4 + oo]);                    \
        acc[2][4 + oo] = fma2((MV)[2], pd, acc[2][4 + oo]);                    \
        acc[3][4 + oo] = fma2((MV)[3], pd, acc[3][4 + oo]);                    \
    }                                                                          \
} while (0)

            DO_J(0, gpp);                          // coeff 1
            long long m1[4];
#pragma unroll
            for (int pp = 0; pp < 4; pp++) m1[pp] = mul2(gpp[pp], dxp[pp]);
            DO_J(1, m1);                           // g*dx
            long long m2[4];
#pragma unroll
            for (int pp = 0; pp < 4; pp++) m2[pp] = mul2(gpp[pp], dyp[pp]);
            DO_J(2, m2);                           // g*dy
            long long mt[4];
#pragma unroll
            for (int pp = 0; pp < 4; pp++) mt[pp] = mul2(m1[pp], dxp[pp]);
            DO_J(3, mt);                           // g*dx^2
#pragma unroll
            for (int pp = 0; pp < 4; pp++) mt[pp] = mul2(m1[pp], dyp[pp]);
            DO_J(4, mt);                           // g*dx*dy
#pragma unroll
            for (int pp = 0; pp < 4; pp++) mt[pp] = mul2(m2[pp], dyp[pp]);
            DO_J(5, mt);                           // g*dy^2
#undef DO_J
        }
    }
#undef PREFETCH

    // ---- Epilogue: stage mix (reuse smem incl. dead P), coalesced I/O ----
    __syncthreads();
    float* stage = smem;              // [256][33] = 33792 B
#pragma unroll
    for (int pp = 0; pp < 4; pp++)
#pragma unroll
        for (int oo = 0; oo < 8; oo++) {
            long long a = acc[pp][oo];
            float lo = __uint_as_float((unsigned)((unsigned long long)a & 0xffffffffu));
            float hi = __uint_as_float((unsigned)((unsigned long long)a >> 32));
            int o = wid * 8 + oo;
            stage[(pg8 + 2 * pp)     * 33 + o] = lo;
            stage[(pg8 + 2 * pp + 1) * 33 + o] = hi;
        }
    __syncthreads();

    size_t lim  = (size_t)total * 31;
    size_t base = (size_t)tile0 * 31;
    for (int e = tid; e < TILE * 31; e += NT) {
        size_t gidx = base + e;
        if (gidx < lim) {
            int rr = e / 31;
            int o  = e - rr * 31;
            out[gidx] = mlp[gidx] * stage[rr * 33 + o];
        }
    }
}

extern "C" void kernel_launch(void* const* d_in, const int* in_sizes, int n_in,
                              void* d_out, int out_size) {
    const float* mlp = (const float*)d_in[0];  // [B,N,31]
    const float* cd  = (const float*)d_in[1];  // [B,N,32,2]
    const float* sig = (const float*)d_in[2];  // [32]
    const float* gw  = (const float*)d_in[3];  // [B,N,32]
    const float* W   = (const float*)d_in[4];  // [32,6,31]

    int total  = in_sizes[3] / 32;             // B*N
    int blocks = (total + TILE - 1) / TILE;    // 1024

    hermite_prep<<<(192 * 32 + 255) / 256, 256>>>(sig, W);

    cudaFuncSetAttribute(hermite_main,
                         cudaFuncAttributeMaxDynamicSharedMemorySize, SMEM_BYTES);
    hermite_main<<<blocks, NT, SMEM_BYTES>>>(mlp, cd, gw, (float*)d_out, total);
}

// round 11
// speedup vs baseline: 1.5464x; 1.0709x over previous
#include <cuda_runtime.h>
#include <stdint.h>

#define NT 128
#define TILE 128        // points per block
#define KC 8            // k-chunk
#define NCHUNK 4        // 32 / KC

// Raw folded weights P[kj][o], kj = k*6+j, o padded to 32. 24 KB.
__device__ float Pg[192 * 32];

__device__ __forceinline__ long long fma2(long long a, long long b, long long c) {
    long long d;
    asm("fma.rn.f32x2 %0, %1, %2, %3;" : "=l"(d) : "l"(a), "l"(b), "l"(c));
    return d;
}
__device__ __forceinline__ long long mul2(long long a, long long b) {
    long long d;
    asm("mul.rn.f32x2 %0, %1, %2;" : "=l"(d) : "l"(a), "l"(b));
    return d;
}
__device__ __forceinline__ long long pack2(float x) {
    long long d;
    asm("mov.b64 %0, {%1, %1};" : "=l"(d) : "f"(x));
    return d;
}
#define LL(f4, half) (*reinterpret_cast<const long long*>(&(f4).half))

__global__ void hermite_prep(const float* __restrict__ sig,
                             const float* __restrict__ W) {
    int i = blockIdx.x * blockDim.x + threadIdx.x;
    if (i >= 192 * 32) return;
    int o  = i & 31;
    int kj = i >> 5;
    int k  = kj / 6;
    int j  = kj - k * 6;
    float val = 0.0f;
    if (o < 31) {
        float s   = sig[k];
        float s2  = s * s;
        float is2 = 1.0f / (s2 + 1e-6f);
        float is4 = 1.0f / (s2 * s2 + 1e-6f);
        const float* Wk = W + k * 186 + o;           // [k][h][o], H=6, O=31
        if      (j == 0) val = Wk[0] - is2 * (Wk[93] + Wk[155]);
        else if (j == 1) val = -is2 * Wk[62];        // * g*dx
        else if (j == 2) val = -is2 * Wk[31];        // * g*dy
        else if (j == 3) val = is4 * Wk[155];        // * g*dx^2
        else if (j == 4) val = is4 * Wk[124];        // * g*dx*dy
        else             val = is4 * Wk[93];         // * g*dy^2
    }
    Pg[kj * 32 + o] = val;
}

extern __shared__ __align__(16) float smem[];
// dxs/dys/gs : [KC][128] each (3 x 4096 B = 12288 B), swizzled cols
// Psh        : [192][32] raw  (24576 B)
// epilogue stage[128][33] = 16896 B reuses the front
#define RAW_FLOATS (KC * TILE)
#define SMEM_BYTES (3 * RAW_FLOATS * 4 + 192 * 32 * 4)   // 36864

// STS: lane kl bits 0-2 -> col bits 2-4; pt bits 0-1 -> 32 distinct banks.
// 16B-granularity preserved (only bits >=2 flipped).
__device__ __forceinline__ int swz(int p, int kl) {
    return p ^ ((p & 32) >> 3) ^ (kl << 2);
}

__global__ void __launch_bounds__(NT, 6)
hermite_main(const float* __restrict__ mlp,
             const float* __restrict__ cd,
             const float* __restrict__ gw,
             float* __restrict__ out,
             int total /* B*N */) {
    float* dxs = smem;
    float* dys = smem + RAW_FLOATS;
    float* gs  = smem + 2 * RAW_FLOATS;
    float* Psh = smem + 3 * RAW_FLOATS;

    const int tid   = threadIdx.x;
    const int wid   = tid >> 5;        // o-group: outputs wid*8 .. wid*8+7
    const int lane  = tid & 31;
    const int pg4   = lane * 4;        // this thread's 4 points
    const int tile0 = blockIdx.x * TILE;

    // ---- Load raw P into SMEM (coalesced) ----
    {
        const float4* src = reinterpret_cast<const float4*>(Pg);
        float4*       dst = reinterpret_cast<float4*>(Psh);
        for (int i = tid; i < (192 * 32) / 4; i += NT) dst[i] = src[i];
    }

    long long acc[2][8];
#pragma unroll
    for (int pp = 0; pp < 2; pp++)
#pragma unroll
        for (int oo = 0; oo < 8; oo++) acc[pp][oo] = 0ll;

#pragma unroll 1
    for (int c = 0; c < NCHUNK; c++) {
        __syncthreads();   // P ready (c=0) / previous chunk's reads done

        // ---- Phase 1: stage raw dx,dy,g for k in [c*KC, c*KC+KC) ----
        // lane->kl fastest (64B cd segments per point); swz -> 32 banks.
#pragma unroll
        for (int it = 0; it < (TILE * KC) / NT; it++) {   // 8 iters
            int item = tid + it * NT;
            int kl   = item & (KC - 1);
            int pt   = item >> 3;
            int n    = tile0 + pt;
            int k    = c * KC + kl;
            float dx = 0.0f, dy = 0.0f, g = 0.0f;
            if (n < total) {
                float2 cc = reinterpret_cast<const float2*>(cd)[(size_t)n * 32 + k];
                dx = cc.x; dy = cc.y;
                g  = gw[(size_t)n * 32 + k];
            }
            int col = swz(pt, kl);
            dxs[kl * TILE + col] = dx;
            dys[kl * TILE + col] = dy;
            gs [kl * TILE + col] = g;
        }
        __syncthreads();

        // ---- Phase 2: 4 pts x 8 outs; P loads warp-uniform (dedup) ----
#pragma unroll 1
        for (int kl = 0; kl < KC; kl++) {
            int colA = swz(pg4, kl);
            float4 ga  = *reinterpret_cast<const float4*>(gs  + kl * TILE + colA);
            float4 dxa = *reinterpret_cast<const float4*>(dxs + kl * TILE + colA);
            float4 dya = *reinterpret_cast<const float4*>(dys + kl * TILE + colA);

            long long gpp[2] = { LL(ga, x), LL(ga, z) };
            long long dxp[2] = { LL(dxa, x), LL(dxa, z) };
            long long dyp[2] = { LL(dya, x), LL(dya, z) };

            const float* Pj = Psh + ((c * KC + kl) * 6) * 32 + wid * 8;

#define DO_J(jj, MV) do {                                                      \
    float4 pa = *reinterpret_cast<const float4*>(Pj + (jj) * 32);              \
    float4 pb = *reinterpret_cast<const float4*>(Pj + (jj) * 32 + 4);          \
    const float* pf = &pa.x;                                                   \
    _Pragma("unroll")                                                          \
    for (int oo = 0; oo < 4; oo++) {                                           \
        long long pd = pack2(pf[oo]);                                          \
        acc[0][oo] = fma2((MV)[0], pd, acc[0][oo]);                            \
        acc[1][oo] = fma2((MV)[1], pd, acc[1][oo]);                            \
    }                                                                          \
    const float* pq = &pb.x;                                                   \
    _Pragma("unroll")                                                          \
    for (int oo = 0; oo < 4; oo++) {                                           \
        long long pd = pack2(pq[oo]);                                          \
        acc[0][4 + oo] = fma2((MV)[0], pd, acc[0][4 + oo]);                    \
        acc[1][4 + oo] = fma2((MV)[1], pd, acc[1][4 + oo]);                    \
    }                                                                          \
} while (0)

            DO_J(0, gpp);                          // coeff 1
            long long m1[2];
#pragma unroll
            for (int pp = 0; pp < 2; pp++) m1[pp] = mul2(gpp[pp], dxp[pp]);
            DO_J(1, m1);                           // g*dx
            long long m2[2];
#pragma unroll
            for (int pp = 0; pp < 2; pp++) m2[pp] = mul2(gpp[pp], dyp[pp]);
            DO_J(2, m2);                           // g*dy
            long long mt[2];
#pragma unroll
            for (int pp = 0; pp < 2; pp++) mt[pp] = mul2(m1[pp], dxp[pp]);
            DO_J(3, mt);                           // g*dx^2
#pragma unroll
            for (int pp = 0; pp < 2; pp++) mt[pp] = mul2(m1[pp], dyp[pp]);
            DO_J(4, mt);                           // g*dx*dy
#pragma unroll
            for (int pp = 0; pp < 2; pp++) mt[pp] = mul2(m2[pp], dyp[pp]);
            DO_J(5, mt);                           // g*dy^2
#undef DO_J
        }
    }

    // ---- Epilogue: stage mix (reuse smem), then coalesced I/O ----
    __syncthreads();
    float* stage = smem;              // [128][33] = 16896 B
#pragma unroll
    for (int pp = 0; pp < 2; pp++)
#pragma unroll
        for (int oo = 0; oo < 8; oo++) {
            long long a = acc[pp][oo];
            float lo = __uint_as_float((unsigned)((unsigned long long)a & 0xffffffffu));
            float hi = __uint_as_float((unsigned)((unsigned long long)a >> 32));
            int o = wid * 8 + oo;
            stage[(pg4 + 2 * pp)     * 33 + o] = lo;
            stage[(pg4 + 2 * pp + 1) * 33 + o] = hi;
        }
    __syncthreads();

    size_t lim  = (size_t)total * 31;
    size_t base = (size_t)tile0 * 31;
    for (int e = tid; e < TILE * 31; e += NT) {
        size_t gidx = base + e;
        if (gidx < lim) {
            int rr = e / 31;
            int o  = e - rr * 31;
            out[gidx] = mlp[gidx] * stage[rr * 33 + o];
        }
    }
}

extern "C" void kernel_launch(void* const* d_in, const int* in_sizes, int n_in,
                              void* d_out, int out_size) {
    const float* mlp = (const float*)d_in[0];  // [B,N,31]
    const float* cd  = (const float*)d_in[1];  // [B,N,32,2]
    const float* sig = (const float*)d_in[2];  // [32]
    const float* gw  = (const float*)d_in[3];  // [B,N,32]
    const float* W   = (const float*)d_in[4];  // [32,6,31]

    int total  = in_sizes[3] / 32;             // B*N
    int blocks = (total + TILE - 1) / TILE;    // 2048

    hermite_prep<<<(192 * 32 + 255) / 256, 256>>>(sig, W);

    cudaFuncSetAttribute(hermite_main,
                         cudaFuncAttributeMaxDynamicSharedMemorySize, SMEM_BYTES);
    hermite_main<<<blocks, NT, SMEM_BYTES>>>(mlp, cd, gw, (float*)d_out, total);
}

// round 12
// speedup vs baseline: 1.6889x; 1.0922x over previous
#include <cuda_runtime.h>
#include <cuda_bf16.h>
#include <stdint.h>

#define NT 128
#define TILE 128
#define KC 8
#define NCHUNK 4

// Precomputed per-lane B fragments: Bfrag[ks(12)][hl(2)][r(2)][nt(4)][lane(32)]
__device__ unsigned Bfrag_g[12 * 2 * 2 * 4 * 32];

__device__ __forceinline__ float P_val(const float* __restrict__ sig,
                                       const float* __restrict__ W,
                                       int kj, int o) {
    if (o >= 31) return 0.0f;
    int k = kj / 6, j = kj - 6 * k;
    float s = sig[k], s2 = s * s;
    float is2 = 1.0f / (s2 + 1e-6f);
    float is4 = 1.0f / (s2 * s2 + 1e-6f);
    const float* Wk = W + k * 186 + o;          // [k][h][o], H=6, O=31
    if (j == 0) return Wk[0] - is2 * (Wk[93] + Wk[155]);
    if (j == 1) return -is2 * Wk[62];           // * g*dx
    if (j == 2) return -is2 * Wk[31];           // * g*dy
    if (j == 3) return is4 * Wk[155];           // * g*dx^2
    if (j == 4) return is4 * Wk[124];           // * g*dx*dy
    return is4 * Wk[93];                        // * g*dy^2
}

__global__ void hermite_prep(const float* __restrict__ sig,
                             const float* __restrict__ W) {
    int i = blockIdx.x * blockDim.x + threadIdx.x;
    if (i >= 6144) return;
    int lane = i & 31;
    int nt   = (i >> 5) & 3;
    int r    = (i >> 7) & 1;
    int hl   = (i >> 8) & 1;
    int ks   = i >> 9;
    int g = lane >> 2, t = lane & 3;
    int n  = nt * 8 + g;                         // output column o
    int k0 = ks * 16 + r * 8 + 2 * t;            // kj index (k dim of mma)
    float va = P_val(sig, W, k0, n);
    float vb = P_val(sig, W, k0 + 1, n);
    unsigned ua = __float_as_uint(va), ub = __float_as_uint(vb);
    unsigned out;
    if (hl == 0) {
        // hi parts: truncate-to-bf16; low half = k-even element
        out = __byte_perm(ua, ub, 0x7632);
    } else {
        float la = va - __uint_as_float(ua & 0xFFFF0000u);
        float lb = vb - __uint_as_float(ub & 0xFFFF0000u);
        __nv_bfloat162 p = __floats2bfloat162_rn(la, lb);   // .x = la (low)
        out = *reinterpret_cast<unsigned*>(&p);
    }
    Bfrag_g[i] = out;
}

// ---- SMEM layout (words) ----
// raw: dxs[8][128], dys, gs  -> 3*1024
// T_hi: 24 rows x 136 words  -> 3264   (T[pair_col][pt], b32 = {kj_even, kj_odd})
// T_lo: 3264
// Bfrag: 6144
#define RAWW 1024
#define T_HI_OFF 3072
#define T_LO_OFF (3072 + 3264)
#define BF_OFF   (3072 + 6528)
#define SMEM_WORDS (BF_OFF + 6144)
#define T_STRIDE 136

extern __shared__ __align__(16) float smem[];

__device__ __forceinline__ void mma_bf16(float& d0, float& d1, float& d2, float& d3,
                                         unsigned a0, unsigned a1, unsigned a2, unsigned a3,
                                         unsigned b0, unsigned b1) {
    asm volatile(
        "mma.sync.aligned.m16n8k16.row.col.f32.bf16.bf16.f32 "
        "{%0,%1,%2,%3}, {%4,%5,%6,%7}, {%8,%9}, {%0,%1,%2,%3};"
        : "+f"(d0), "+f"(d1), "+f"(d2), "+f"(d3)
        : "r"(a0), "r"(a1), "r"(a2), "r"(a3), "r"(b0), "r"(b1));
}

__global__ void __launch_bounds__(NT, 3)
hermite_main(const float* __restrict__ mlp,
             const float* __restrict__ cd,
             const float* __restrict__ gw,
             float* __restrict__ out,
             int total) {
    float* dxs = smem;
    float* dys = smem + RAWW;
    float* gs  = smem + 2 * RAWW;
    unsigned* Thi = reinterpret_cast<unsigned*>(smem + T_HI_OFF);
    unsigned* Tlo = reinterpret_cast<unsigned*>(smem + T_LO_OFF);
    unsigned* Bs  = reinterpret_cast<unsigned*>(smem + BF_OFF);

    const int tid   = threadIdx.x;
    const int wid   = tid >> 5;
    const int lane  = tid & 31;
    const int g     = lane >> 2;
    const int t     = lane & 3;
    const int mw    = wid & 1;        // m half: pts [64mw, 64mw+64)
    const int nw    = wid >> 1;       // n half: outs [16nw, 16nw+16)
    const int tile0 = blockIdx.x * TILE;

    // ---- Copy B fragments to SMEM (coalesced) ----
    {
        const float4* src = reinterpret_cast<const float4*>(Bfrag_g);
        float4* dst = reinterpret_cast<float4*>(Bs);
        for (int i = tid; i < 6144 / 4; i += NT) dst[i] = src[i];
    }

    float acc[4][2][4];
#pragma unroll
    for (int mi = 0; mi < 4; mi++)
#pragma unroll
        for (int ni = 0; ni < 2; ni++)
#pragma unroll
            for (int q = 0; q < 4; q++) acc[mi][ni][q] = 0.0f;

#pragma unroll 1
    for (int c = 0; c < NCHUNK; c++) {
        __syncthreads();   // Bfrag ready (c=0) / previous chunk T reads done

        // ---- Phase 1: coalesced raw staging (lane->kl fastest) ----
#pragma unroll
        for (int it = 0; it < 8; it++) {
            int item = tid + it * NT;
            int kl   = item & 7;
            int pt   = item >> 3;
            int n    = tile0 + pt;
            int k    = c * KC + kl;
            float dx = 0.0f, dy = 0.0f, gg = 0.0f;
            if (n < total) {
                float2 cc = reinterpret_cast<const float2*>(cd)[(size_t)n * 32 + k];
                dx = cc.x; dy = cc.y;
                gg = gw[(size_t)n * 32 + k];
            }
            int col = pt ^ ((pt & 32) >> 3) ^ (kl << 2);
            dxs[kl * TILE + col] = dx;
            dys[kl * TILE + col] = dy;
            gs [kl * TILE + col] = gg;
        }
        __syncthreads();

        // ---- Monomials -> bf16 hi/lo pairs -> T[pair][pt] (thread = pt) ----
#pragma unroll
        for (int kl = 0; kl < KC; kl++) {
            int col = kl * TILE + (tid ^ ((tid & 32) >> 3) ^ (kl << 2));
            float dx = dxs[col], dy = dys[col], gg = gs[col];
            float m1 = gg * dx, m2 = gg * dy;
            float m3 = m1 * dx, m4 = m1 * dy, m5 = m2 * dy;
            float pa[3] = { gg, m2, m4 };   // kj even of each pair
            float pb[3] = { m1, m3, m5 };   // kj odd
#pragma unroll
            for (int u = 0; u < 3; u++) {
                unsigned ua = __float_as_uint(pa[u]);
                unsigned ub = __float_as_uint(pb[u]);
                unsigned hi32 = __byte_perm(ua, ub, 0x7632);
                float la = pa[u] - __uint_as_float(ua & 0xFFFF0000u);
                float lb = pb[u] - __uint_as_float(ub & 0xFFFF0000u);
                __nv_bfloat162 p = __floats2bfloat162_rn(la, lb);
                int row = 3 * kl + u;                  // pair col 0..23
                Thi[row * T_STRIDE + tid] = hi32;
                Tlo[row * T_STRIDE + tid] = *reinterpret_cast<unsigned*>(&p);
            }
        }
        __syncthreads();

        // ---- MMA sweep: 3 k-steps x 4 m-tiles x 2 n-tiles x 3 passes ----
#pragma unroll
        for (int ksl = 0; ksl < 3; ksl++) {
            int ks = c * 3 + ksl;
            unsigned bh[2][2], bl[2][2];
#pragma unroll
            for (int ni = 0; ni < 2; ni++) {
                int nt = 2 * nw + ni;
#pragma unroll
                for (int r = 0; r < 2; r++) {
                    bh[ni][r] = Bs[(((ks * 2 + 0) * 2 + r) * 4 + nt) * 32 + lane];
                    bl[ni][r] = Bs[(((ks * 2 + 1) * 2 + r) * 4 + nt) * 32 + lane];
                }
            }
#pragma unroll
            for (int mi = 0; mi < 4; mi++) {
                int pt0 = (4 * mw + mi) * 16 + g;      // row for a0/a2
                int rA = (8 * ksl + t) * T_STRIDE;     // pair col t
                int rC = (8 * ksl + t + 4) * T_STRIDE; // pair col t+4 (kj+8)
                unsigned ah0 = Thi[rA + pt0],     ah1 = Thi[rA + pt0 + 8];
                unsigned ah2 = Thi[rC + pt0],     ah3 = Thi[rC + pt0 + 8];
                unsigned al0 = Tlo[rA + pt0],     al1 = Tlo[rA + pt0 + 8];
                unsigned al2 = Tlo[rC + pt0],     al3 = Tlo[rC + pt0 + 8];
#pragma unroll
                for (int ni = 0; ni < 2; ni++) {
                    float* d = acc[mi][ni];
                    mma_bf16(d[0], d[1], d[2], d[3], ah0, ah1, ah2, ah3,
                             bh[ni][0], bh[ni][1]);
                    mma_bf16(d[0], d[1], d[2], d[3], ah0, ah1, ah2, ah3,
                             bl[ni][0], bl[ni][1]);
                    mma_bf16(d[0], d[1], d[2], d[3], al0, al1, al2, al3,
                             bh[ni][0], bh[ni][1]);
                }
            }
        }
    }

    // ---- Epilogue: fragments -> stage[128][33] -> coalesced out = mlp*mix ----
    __syncthreads();
    float* stage = smem;              // 4224 words, fits raw+T region
#pragma unroll
    for (int mi = 0; mi < 4; mi++) {
        int row0 = (4 * mw + mi) * 16 + g;
#pragma unroll
        for (int ni = 0; ni < 2; ni++) {
            int o0 = (2 * nw + ni) * 8 + 2 * t;
            stage[row0 * 33 + o0]           = acc[mi][ni][0];
            stage[row0 * 33 + o0 + 1]       = acc[mi][ni][1];
            stage[(row0 + 8) * 33 + o0]     = acc[mi][ni][2];
            stage[(row0 + 8) * 33 + o0 + 1] = acc[mi][ni][3];
        }
    }
    __syncthreads();

    size_t lim  = (size_t)total * 31;
    size_t base = (size_t)tile0 * 31;
    for (int e = tid; e < TILE * 31; e += NT) {
        size_t gidx = base + e;
        if (gidx < lim) {
            int rr = e / 31;
            int o  = e - rr * 31;
            out[gidx] = mlp[gidx] * stage[rr * 33 + o];
        }
    }
}

extern "C" void kernel_launch(void* const* d_in, const int* in_sizes, int n_in,
                              void* d_out, int out_size) {
    const float* mlp = (const float*)d_in[0];  // [B,N,31]
    const float* cd  = (const float*)d_in[1];  // [B,N,32,2]
    const float* sig = (const float*)d_in[2];  // [32]
    const float* gw  = (const float*)d_in[3];  // [B,N,32]
    const float* W   = (const float*)d_in[4];  // [32,6,31]

    int total  = in_sizes[3] / 32;             // B*N = 262144
    int blocks = (total + TILE - 1) / TILE;    // 2048

    hermite_prep<<<(6144 + 255) / 256, 256>>>(sig, W);

    cudaFuncSetAttribute(hermite_main,
                         cudaFuncAttributeMaxDynamicSharedMemorySize,
                         SMEM_WORDS * 4);
    hermite_main<<<blocks, NT, SMEM_WORDS * 4>>>(mlp, cd, gw, (float*)d_out, total);
}

// round 13
// speedup vs baseline: 2.1268x; 1.2593x over previous
#include <cuda_runtime.h>
#include <cuda_bf16.h>
#include <stdint.h>

#define NT 128
#define TILE 128
#define KC 8
#define NCHUNK 4

// Precomputed per-lane B fragments: Bfrag[ks(12)][hl(2)][r(2)][nt(4)][lane(32)]
__device__ unsigned Bfrag_g[12 * 2 * 2 * 4 * 32];

__device__ __forceinline__ float P_val(const float* __restrict__ sig,
                                       const float* __restrict__ W,
                                       int kj, int o) {
    if (o >= 31) return 0.0f;
    int k = kj / 6, j = kj - 6 * k;
    float s = sig[k], s2 = s * s;
    float is2 = 1.0f / (s2 + 1e-6f);
    float is4 = 1.0f / (s2 * s2 + 1e-6f);
    const float* Wk = W + k * 186 + o;          // [k][h][o], H=6, O=31
    if (j == 0) return Wk[0] - is2 * (Wk[93] + Wk[155]);
    if (j == 1) return -is2 * Wk[62];           // * g*dx
    if (j == 2) return -is2 * Wk[31];           // * g*dy
    if (j == 3) return is4 * Wk[155];           // * g*dx^2
    if (j == 4) return is4 * Wk[124];           // * g*dx*dy
    return is4 * Wk[93];                        // * g*dy^2
}

__global__ void hermite_prep(const float* __restrict__ sig,
                             const float* __restrict__ W) {
    int i = blockIdx.x * blockDim.x + threadIdx.x;
    if (i >= 6144) return;
    int lane = i & 31;
    int nt   = (i >> 5) & 3;
    int r    = (i >> 7) & 1;
    int hl   = (i >> 8) & 1;
    int ks   = i >> 9;
    int g = lane >> 2, t = lane & 3;
    int n  = nt * 8 + g;                         // output column o
    int k0 = ks * 16 + r * 8 + 2 * t;            // kj index (k dim of mma)
    float va = P_val(sig, W, k0, n);
    float vb = P_val(sig, W, k0 + 1, n);
    unsigned ua = __float_as_uint(va), ub = __float_as_uint(vb);
    unsigned o32;
    if (hl == 0) {
        o32 = __byte_perm(ua, ub, 0x7632);       // bf16 hi parts, low=k-even
    } else {
        float la = va - __uint_as_float(ua & 0xFFFF0000u);
        float lb = vb - __uint_as_float(ub & 0xFFFF0000u);
        __nv_bfloat162 p = __floats2bfloat162_rn(la, lb);
        o32 = *reinterpret_cast<unsigned*>(&p);
    }
    Bfrag_g[i] = o32;
}

// ---- SMEM layout (words) ----
// raw: dxs[8][128], dys, gs  -> 3*1024
// T_hi: 24 rows x 136 words  -> 3264  (T[pair_col][c(pt)], b32 = {kj_even, kj_odd})
// T_lo: 3264
#define RAWW 1024
#define T_HI_OFF 3072
#define T_LO_OFF (3072 + 3264)
#define SMEM_WORDS (T_LO_OFF + 3264)    // 9600 words = 38400 B
#define T_STRIDE 136                     // ≡ 8 (mod 32): LDS.64 conflict-free

extern __shared__ __align__(16) float smem[];

__device__ __forceinline__ void mma_bf16(float& d0, float& d1, float& d2, float& d3,
                                         unsigned a0, unsigned a1, unsigned a2, unsigned a3,
                                         unsigned b0, unsigned b1) {
    asm volatile(
        "mma.sync.aligned.m16n8k16.row.col.f32.bf16.bf16.f32 "
        "{%0,%1,%2,%3}, {%4,%5,%6,%7}, {%8,%9}, {%0,%1,%2,%3};"
        : "+f"(d0), "+f"(d1), "+f"(d2), "+f"(d3)
        : "r"(a0), "r"(a1), "r"(a2), "r"(a3), "r"(b0), "r"(b1));
}

// interleaved point->column map: (pt, pt+8) become adjacent words
__device__ __forceinline__ int cmap(int pt) {
    return (pt >> 4) * 16 + (pt & 7) * 2 + ((pt >> 3) & 1);
}

__global__ void __launch_bounds__(NT, 4)
hermite_main(const float* __restrict__ mlp,
             const float* __restrict__ cd,
             const float* __restrict__ gw,
             float* __restrict__ out,
             int total) {
    float* dxs = smem;
    float* dys = smem + RAWW;
    float* gs  = smem + 2 * RAWW;
    unsigned* Thi = reinterpret_cast<unsigned*>(smem + T_HI_OFF);
    unsigned* Tlo = reinterpret_cast<unsigned*>(smem + T_LO_OFF);

    const int tid   = threadIdx.x;
    const int wid   = tid >> 5;
    const int lane  = tid & 31;
    const int g     = lane >> 2;
    const int t     = lane & 3;
    const int mw    = wid & 1;        // m half: pts [64mw, 64mw+64)
    const int nw    = wid >> 1;       // n half: outs [16nw, 16nw+16)
    const int tile0 = blockIdx.x * TILE;
    const int ctid  = cmap(tid);      // this thread's T column

    float acc[4][2][4];
#pragma unroll
    for (int mi = 0; mi < 4; mi++)
#pragma unroll
        for (int ni = 0; ni < 2; ni++)
#pragma unroll
            for (int q = 0; q < 4; q++) acc[mi][ni][q] = 0.0f;

#pragma unroll 1
    for (int c = 0; c < NCHUNK; c++) {
        __syncthreads();   // previous chunk's T reads done

        // ---- Phase 1: coalesced raw staging (lane->kl fastest) ----
#pragma unroll
        for (int it = 0; it < 8; it++) {
            int item = tid + it * NT;
            int kl   = item & 7;
            int pt   = item >> 3;
            int n    = tile0 + pt;
            int k    = c * KC + kl;
            float dx = 0.0f, dy = 0.0f, gg = 0.0f;
            if (n < total) {
                float2 cc = reinterpret_cast<const float2*>(cd)[(size_t)n * 32 + k];
                dx = cc.x; dy = cc.y;
                gg = gw[(size_t)n * 32 + k];
            }
            int col = pt ^ ((pt & 32) >> 3) ^ (kl << 2);
            dxs[kl * TILE + col] = dx;
            dys[kl * TILE + col] = dy;
            gs [kl * TILE + col] = gg;
        }
        __syncthreads();

        // ---- Monomials -> bf16 hi/lo pairs -> T[pair][c(pt)] (thread = pt) ----
#pragma unroll
        for (int kl = 0; kl < KC; kl++) {
            int col = kl * TILE + (tid ^ ((tid & 32) >> 3) ^ (kl << 2));
            float dx = dxs[col], dy = dys[col], gg = gs[col];
            float m1 = gg * dx, m2 = gg * dy;
            float m3 = m1 * dx, m4 = m1 * dy, m5 = m2 * dy;
            float pa[3] = { gg, m2, m4 };   // kj even of each pair
            float pb[3] = { m1, m3, m5 };   // kj odd
#pragma unroll
            for (int u = 0; u < 3; u++) {
                unsigned ua = __float_as_uint(pa[u]);
                unsigned ub = __float_as_uint(pb[u]);
                unsigned hi32 = __byte_perm(ua, ub, 0x7632);
                float la = pa[u] - __uint_as_float(ua & 0xFFFF0000u);
                float lb = pb[u] - __uint_as_float(ub & 0xFFFF0000u);
                __nv_bfloat162 p = __floats2bfloat162_rn(la, lb);
                int row = 3 * kl + u;                  // pair col 0..23
                Thi[row * T_STRIDE + ctid] = hi32;
                Tlo[row * T_STRIDE + ctid] = *reinterpret_cast<unsigned*>(&p);
            }
        }
        __syncthreads();

        // ---- MMA sweep: 3 k-steps x 4 m-tiles x 2 n-tiles x 3 passes ----
#pragma unroll
        for (int ksl = 0; ksl < 3; ksl++) {
            int ks = c * 3 + ksl;
            unsigned bh[2][2], bl[2][2];
#pragma unroll
            for (int ni = 0; ni < 2; ni++) {
                int nt = 2 * nw + ni;
#pragma unroll
                for (int r = 0; r < 2; r++) {
                    bh[ni][r] = __ldg(&Bfrag_g[(((ks * 2 + 0) * 2 + r) * 4 + nt) * 32 + lane]);
                    bl[ni][r] = __ldg(&Bfrag_g[(((ks * 2 + 1) * 2 + r) * 4 + nt) * 32 + lane]);
                }
            }
#pragma unroll
            for (int mi = 0; mi < 4; mi++) {
                int c0 = (4 * mw + mi) * 16 + 2 * g;   // {pt0, pt0+8} adjacent
                int rA = (8 * ksl + t) * T_STRIDE;     // pair col t
                int rC = (8 * ksl + t + 4) * T_STRIDE; // pair col t+4 (kj+8)
                uint2 ahA = *reinterpret_cast<const uint2*>(&Thi[rA + c0]);  // a0,a1
                uint2 ahC = *reinterpret_cast<const uint2*>(&Thi[rC + c0]);  // a2,a3
                uint2 alA = *reinterpret_cast<const uint2*>(&Tlo[rA + c0]);
                uint2 alC = *reinterpret_cast<const uint2*>(&Tlo[rC + c0]);
#pragma unroll
                for (int ni = 0; ni < 2; ni++) {
                    float* d = acc[mi][ni];
                    mma_bf16(d[0], d[1], d[2], d[3], ahA.x, ahA.y, ahC.x, ahC.y,
                             bh[ni][0], bh[ni][1]);
                    mma_bf16(d[0], d[1], d[2], d[3], ahA.x, ahA.y, ahC.x, ahC.y,
                             bl[ni][0], bl[ni][1]);
                    mma_bf16(d[0], d[1], d[2], d[3], alA.x, alA.y, alC.x, alC.y,
                             bh[ni][0], bh[ni][1]);
                }
            }
        }
    }

    // ---- Epilogue: fragments -> stage[128][33] -> coalesced out = mlp*mix ----
    __syncthreads();
    float* stage = smem;              // 4224 words <= 9600
#pragma unroll
    for (int mi = 0; mi < 4; mi++) {
        int row0 = (4 * mw + mi) * 16 + g;
#pragma unroll
        for (int ni = 0; ni < 2; ni++) {
            int o0 = (2 * nw + ni) * 8 + 2 * t;
            stage[row0 * 33 + o0]           = acc[mi][ni][0];
            stage[row0 * 33 + o0 + 1]       = acc[mi][ni][1];
            stage[(row0 + 8) * 33 + o0]     = acc[mi][ni][2];
            stage[(row0 + 8) * 33 + o0 + 1] = acc[mi][ni][3];
        }
    }
    __syncthreads();

    size_t lim  = (size_t)total * 31;
    size_t base = (size_t)tile0 * 31;
    for (int e = tid; e < TILE * 31; e += NT) {
        size_t gidx = base + e;
        if (gidx < lim) {
            int rr = e / 31;
            int o  = e - rr * 31;
            out[gidx] = mlp[gidx] * stage[rr * 33 + o];
        }
    }
}

extern "C" void kernel_launch(void* const* d_in, const int* in_sizes, int n_in,
                              void* d_out, int out_size) {
    const float* mlp = (const float*)d_in[0];  // [B,N,31]
    const float* cd  = (const float*)d_in[1];  // [B,N,32,2]
    const float* sig = (const float*)d_in[2];  // [32]
    const float* gw  = (const float*)d_in[3];  // [B,N,32]
    const float* W   = (const float*)d_in[4];  // [32,6,31]

    int total  = in_sizes[3] / 32;             // B*N = 262144
    int blocks = (total + TILE - 1) / TILE;    // 2048

    hermite_prep<<<(6144 + 255) / 256, 256>>>(sig, W);

    cudaFuncSetAttribute(hermite_main,
                         cudaFuncAttributeMaxDynamicSharedMemorySize,
                         SMEM_WORDS * 4);
    hermite_main<<<blocks, NT, SMEM_WORDS * 4>>>(mlp, cd, gw, (float*)d_out, total);
}